// round 10
// baseline (speedup 1.0000x reference)
#include <cuda_runtime.h>
#include <cuda_bf16.h>

// Problem constants (fixed by the dataset)
#define MAXN 50000
#define MAXE 800000

// ---------------- scratch (__device__ globals; allocation-free) ----------------
__device__ float g_q [MAXN * 128];
__device__ float g_Ak[MAXN * 128];
__device__ float g_Bk[MAXN * 128];
__device__ float g_Av[MAXN * 128];
__device__ float g_Bv[MAXN * 128];
__device__ float g_s  [(size_t)MAXE * 16];
__device__ float g_vw [(size_t)MAXE * 16];
__device__ float g_smax[MAXN * 16];
__device__ float g_den [MAXN * 16];
__device__ float g_num [MAXN * 48];

__device__ __forceinline__ void atomicMaxFloat(float* addr, float val) {
    // valid for mixed signs with init = -inf
    if (val >= 0.0f) atomicMax((int*)addr, __float_as_int(val));
    else             atomicMin((unsigned int*)addr, __float_as_uint(val));
}

// ---------------- init ----------------
__global__ void init_kernel(int N) {
    int i = blockIdx.x * blockDim.x + threadIdx.x;
    if (i < N * 16) {
        g_smax[i] = __int_as_float(0xff800000u); // -inf
        g_den[i]  = 0.0f;
    }
    if (i < N * 48) g_num[i] = 0.0f;
}

// ---------------- shared 64x128 register-tiled GEMM helper ----------------
// 256 threads: tx = tid&31 -> 4 cols (ch = tx*4), ty = tid>>5 -> 8 rows (r = ty*8+j)
__device__ __forceinline__ void gemm64x128(const float* __restrict__ Ws,
                                           const float* __restrict__ Xs,
                                           int tx, int ty, float acc[8][4]) {
#pragma unroll
    for (int j = 0; j < 8; j++) { acc[j][0]=0.f; acc[j][1]=0.f; acc[j][2]=0.f; acc[j][3]=0.f; }
    const float* wp = Ws + tx * 4;
    const float* xp = Xs + (ty * 8) * 128;
#pragma unroll 4
    for (int k = 0; k < 128; k++) {
        float4 w = *(const float4*)(wp + k * 128);
#pragma unroll
        for (int j = 0; j < 8; j++) {
            float x = xp[j * 128 + k];
            acc[j][0] = fmaf(x, w.x, acc[j][0]);
            acc[j][1] = fmaf(x, w.y, acc[j][1]);
            acc[j][2] = fmaf(x, w.z, acc[j][2]);
            acc[j][3] = fmaf(x, w.w, acc[j][3]);
        }
    }
}

// ---------------- node kernel: q (full MLP) + Ak/Bk/Av/Bv ----------------
#define NODE_SMEM_BYTES ((64*128 + 128*128) * 4)

__global__ void __launch_bounds__(256) node_kernel(
    const float* __restrict__ h,
    const float* __restrict__ xkW1, const float* __restrict__ xvW1,
    const float* __restrict__ xqW1, const float* __restrict__ xqb1,
    const float* __restrict__ xqg,  const float* __restrict__ xqbe,
    const float* __restrict__ xqW2, const float* __restrict__ xqb2,
    int N)
{
    extern __shared__ float sm[];
    float* Hs = sm;            // 64*128  (reused as LN buffer for q path)
    float* Ws = sm + 64 * 128; // 128*128
    const int tid = threadIdx.x;
    const int n0  = blockIdx.x * 64;

    for (int idx = tid; idx < 64 * 128; idx += 256) {
        int r = idx >> 7, c = idx & 127;
        int n = n0 + r;
        Hs[idx] = (n < N) ? h[(size_t)n * 128 + c] : 0.0f;
    }
    const int tx = tid & 31, ty = tid >> 5;

    // 4 node-partial GEMMs
    const float* srcs[4] = { xkW1 + 80*128, xkW1 + 208*128, xvW1 + 80*128, xvW1 + 208*128 };
    float* outs[4] = { g_Ak, g_Bk, g_Av, g_Bv };
    for (int m = 0; m < 4; m++) {
        __syncthreads();
        for (int idx = tid; idx < 128 * 128; idx += 256) Ws[idx] = srcs[m][idx];
        __syncthreads();
        float acc[8][4];
        gemm64x128(Ws, Hs, tx, ty, acc);
#pragma unroll
        for (int j = 0; j < 8; j++) {
            int n = n0 + ty * 8 + j;
            if (n < N) {
                float4 o = make_float4(acc[j][0], acc[j][1], acc[j][2], acc[j][3]);
                *(float4*)(outs[m] + (size_t)n * 128 + tx * 4) = o;
            }
        }
    }

    // q layer 1
    __syncthreads();
    for (int idx = tid; idx < 128 * 128; idx += 256) Ws[idx] = xqW1[idx];
    __syncthreads();
    {
        float acc[8][4];
        gemm64x128(Ws, Hs, tx, ty, acc);
        float4 b1 = *(const float4*)(xqb1 + tx * 4);
        __syncthreads(); // all reads of Hs done; safe to overwrite
#pragma unroll
        for (int j = 0; j < 8; j++) {
            int r = ty * 8 + j;
            float4 o = make_float4(acc[j][0]+b1.x, acc[j][1]+b1.y, acc[j][2]+b1.z, acc[j][3]+b1.w);
            *(float4*)(Hs + r * 128 + tx * 4) = o;
        }
    }
    __syncthreads();

    // LayerNorm + ReLU on Hs rows
    {
        const int lane = tid & 31, w = tid >> 5;
        for (int r = w; r < 64; r += 8) {
            float* row = Hs + r * 128;
            float v0 = row[lane], v1 = row[lane+32], v2 = row[lane+64], v3 = row[lane+96];
            float s1 = v0+v1+v2+v3;
            float s2 = v0*v0+v1*v1+v2*v2+v3*v3;
#pragma unroll
            for (int o = 16; o > 0; o >>= 1) {
                s1 += __shfl_xor_sync(0xffffffffu, s1, o);
                s2 += __shfl_xor_sync(0xffffffffu, s2, o);
            }
            float mean = s1 * 0.0078125f;
            float var  = fmaxf(s2 * 0.0078125f - mean * mean, 0.0f);
            float rstd = rsqrtf(var + 1e-5f);
            row[lane]    = fmaxf((v0-mean)*rstd*xqg[lane]    + xqbe[lane],    0.0f);
            row[lane+32] = fmaxf((v1-mean)*rstd*xqg[lane+32] + xqbe[lane+32], 0.0f);
            row[lane+64] = fmaxf((v2-mean)*rstd*xqg[lane+64] + xqbe[lane+64], 0.0f);
            row[lane+96] = fmaxf((v3-mean)*rstd*xqg[lane+96] + xqbe[lane+96], 0.0f);
        }
    }

    // q layer 2
    __syncthreads();
    for (int idx = tid; idx < 128 * 128; idx += 256) Ws[idx] = xqW2[idx];
    __syncthreads();
    {
        float acc[8][4];
        gemm64x128(Ws, Hs, tx, ty, acc);
        float4 b2 = *(const float4*)(xqb2 + tx * 4);
#pragma unroll
        for (int j = 0; j < 8; j++) {
            int n = n0 + ty * 8 + j;
            if (n < N) {
                float4 o = make_float4(acc[j][0]+b2.x, acc[j][1]+b2.y, acc[j][2]+b2.z, acc[j][3]+b2.w);
                *(float4*)(g_q + (size_t)n * 128 + tx * 4) = o;
            }
        }
    }
}

// ---------------- edge kernel ----------------
#define US 260  // padded Us row stride (floats): breaks phase-B bank conflicts
// shared floats: Ws 20480 | Xs 5120 | Us 64*260=16640 | ews 64 | sdst 64 | ssrc 64 | ewWs 64
#define EDGE_SMEM_FLOATS (20480 + 5120 + 64*US + 64 + 64 + 64 + 64)
#define EDGE_SMEM_BYTES  (EDGE_SMEM_FLOATS * 4)

__global__ void __launch_bounds__(256) edge_kernel(
    const float* __restrict__ ef, const float* __restrict__ rf,
    const int*   __restrict__ eidx,
    const float* __restrict__ xkW1, const float* __restrict__ xkb1,
    const float* __restrict__ xkg,  const float* __restrict__ xkbe,
    const float* __restrict__ xkW2, const float* __restrict__ xkb2,
    const float* __restrict__ xvW1, const float* __restrict__ xvb1,
    const float* __restrict__ xvg,  const float* __restrict__ xvbe,
    const float* __restrict__ xvW2, const float* __restrict__ xvb2,
    const float* __restrict__ ewW,  const float* __restrict__ ewb,
    int E)
{
    extern __shared__ float sm[];
    float* Ws   = sm;                    // phase A: [80][256]; phase B: Wk2[128][128] + Wv2[128][16]
    float* Xs   = sm + 20480;            // [80][64] : (ef||rf) transposed
    float* Us   = sm + 20480 + 5120;     // [64][US] : layer-1 pre/post activations (k net cols 0..127, v net 128..255)
    float* ews  = Us + 64 * US;          // [64]
    int*   sdst = (int*)(ews + 64);      // [64]
    int*   ssrc = sdst + 64;             // [64]
    float* ewWs = (float*)(ssrc + 64);   // [64]

    const int  tid = threadIdx.x;
    const long e0  = (long)blockIdx.x * 64;

    if (tid < 64) {
        long ge = e0 + tid;
        ssrc[tid] = (ge < E) ? eidx[ge]     : 0;
        sdst[tid] = (ge < E) ? eidx[E + ge] : 0;
    }
    if (tid >= 64 && tid < 128) ewWs[tid - 64] = ewW[tid - 64];

    // X tile (clamped loads for tail safety)
    for (int idx = tid; idx < 64 * 16; idx += 256) {
        int e = idx >> 4, k = idx & 15;
        long ge = e0 + e; if (ge > E - 1) ge = E - 1;
        Xs[k * 64 + e] = ef[ge * 16 + k];
    }
    for (int idx = tid; idx < 64 * 64; idx += 256) {
        int e = idx >> 6, k = idx & 63;
        long ge = e0 + e; if (ge > E - 1) ge = E - 1;
        Xs[(16 + k) * 64 + e] = rf[ge * 64 + k];
    }
    // phase-A weights: rows 0..79 of both W1s, k net in cols 0..127, v net in 128..255
    for (int idx = tid; idx < 80 * 128; idx += 256) {
        int r = idx >> 7, c = idx & 127;
        Ws[r * 256 + c]       = xkW1[idx];
        Ws[r * 256 + 128 + c] = xvW1[idx];
    }
    __syncthreads();

    // -------- Phase A: [64 edges][256 ch] = Xs[64][80] @ Ws[80][256] + bias + gathered node partials --------
    {
        const int tx = tid & 31;  // 8 channels each -> 256
        const int ty = tid >> 5;  // 8 edges each -> 64
        float acc[8][8];
#pragma unroll
        for (int j = 0; j < 8; j++)
#pragma unroll
            for (int c = 0; c < 8; c++) acc[j][c] = 0.0f;

        const float* wp = Ws + tx * 8;
        const float* xp = Xs + ty * 8;
#pragma unroll 2
        for (int k = 0; k < 80; k++) {
            float4 w0 = *(const float4*)(wp + k * 256);
            float4 w1 = *(const float4*)(wp + k * 256 + 4);
            float4 x0 = *(const float4*)(xp + k * 64);
            float4 x1 = *(const float4*)(xp + k * 64 + 4);
            float xv[8] = {x0.x,x0.y,x0.z,x0.w,x1.x,x1.y,x1.z,x1.w};
            float wv[8] = {w0.x,w0.y,w0.z,w0.w,w1.x,w1.y,w1.z,w1.w};
#pragma unroll
            for (int j = 0; j < 8; j++)
#pragma unroll
                for (int c = 0; c < 8; c++)
                    acc[j][c] = fmaf(xv[j], wv[c], acc[j][c]);
        }

        const bool  isV = (tx >= 16);
        const float* Ap  = isV ? g_Av : g_Ak;
        const float* Bp  = isV ? g_Bv : g_Bk;
        const float* b1p = isV ? xvb1 : xkb1;
        const int ch  = (tx & 15) * 8;
        const int col = tx * 8;
        float4 bb0 = *(const float4*)(b1p + ch);
        float4 bb1 = *(const float4*)(b1p + ch + 4);
#pragma unroll
        for (int j = 0; j < 8; j++) {
            int e = ty * 8 + j;
            int d = sdst[e], s = ssrc[e];
            float4 a0 = *(const float4*)(Ap + (size_t)d * 128 + ch);
            float4 a1 = *(const float4*)(Ap + (size_t)d * 128 + ch + 4);
            float4 c0 = *(const float4*)(Bp + (size_t)s * 128 + ch);
            float4 c1 = *(const float4*)(Bp + (size_t)s * 128 + ch + 4);
            float4 o0 = make_float4(acc[j][0]+bb0.x+a0.x+c0.x, acc[j][1]+bb0.y+a0.y+c0.y,
                                    acc[j][2]+bb0.z+a0.z+c0.z, acc[j][3]+bb0.w+a0.w+c0.w);
            float4 o1 = make_float4(acc[j][4]+bb1.x+a1.x+c1.x, acc[j][5]+bb1.y+a1.y+c1.y,
                                    acc[j][6]+bb1.z+a1.z+c1.z, acc[j][7]+bb1.w+a1.w+c1.w);
            *(float4*)(Us + e * US + col)     = o0;
            *(float4*)(Us + e * US + col + 4) = o1;
        }
    }
    __syncthreads();

    // -------- LayerNorm + ReLU (128 rows: 64 edges x 2 nets) + edge weights --------
    {
        const int lane = tid & 31, w = tid >> 5;
        for (int r = w; r < 128; r += 8) {
            const int e = r >> 1, net = r & 1;
            float* row = Us + e * US + net * 128;
            float v0 = row[lane], v1 = row[lane+32], v2 = row[lane+64], v3 = row[lane+96];
            float s1 = v0+v1+v2+v3;
            float s2 = v0*v0+v1*v1+v2*v2+v3*v3;
#pragma unroll
            for (int o = 16; o > 0; o >>= 1) {
                s1 += __shfl_xor_sync(0xffffffffu, s1, o);
                s2 += __shfl_xor_sync(0xffffffffu, s2, o);
            }
            float mean = s1 * 0.0078125f;
            float var  = fmaxf(s2 * 0.0078125f - mean * mean, 0.0f);
            float rstd = rsqrtf(var + 1e-5f);
            const float* gp  = net ? xvg  : xkg;
            const float* bep = net ? xvbe : xkbe;
            row[lane]    = fmaxf((v0-mean)*rstd*gp[lane]    + bep[lane],    0.0f);
            row[lane+32] = fmaxf((v1-mean)*rstd*gp[lane+32] + bep[lane+32], 0.0f);
            row[lane+64] = fmaxf((v2-mean)*rstd*gp[lane+64] + bep[lane+64], 0.0f);
            row[lane+96] = fmaxf((v3-mean)*rstd*gp[lane+96] + bep[lane+96], 0.0f);
        }
        if (tid < 64) {
            float a = ewb[0];
#pragma unroll 8
            for (int i = 0; i < 64; i++) a = fmaf(Xs[(16 + i) * 64 + tid], ewWs[i], a);
            ews[tid] = 1.0f / (1.0f + __expf(-a));
        }
    }
    __syncthreads();

    // phase-B weights into the Ws region
    for (int idx = tid; idx < 128 * 128; idx += 256) Ws[idx] = xkW2[idx];
    for (int idx = tid; idx < 128 * 16;  idx += 256) Ws[16384 + idx] = xvW2[idx];
    __syncthreads();

    // -------- Phase B1: k = U_k @ Wk2 + b ; s = dot(q[dst], k)/sqrt(8) ; segment max --------
    {
        const int tx = tid & 31;  // 4 channels each -> 128 (half of one head)
        const int ty = tid >> 5;  // 8 edges each -> 64
        float acc[8][4];
#pragma unroll
        for (int j = 0; j < 8; j++) { acc[j][0]=0.f; acc[j][1]=0.f; acc[j][2]=0.f; acc[j][3]=0.f; }
        const float* wp = Ws + tx * 4;
        const float* up = Us + (ty * 8) * US;
#pragma unroll 4
        for (int k = 0; k < 128; k++) {
            float4 w = *(const float4*)(wp + k * 128);
#pragma unroll
            for (int j = 0; j < 8; j++) {
                float x = up[j * US + k];
                acc[j][0] = fmaf(x, w.x, acc[j][0]);
                acc[j][1] = fmaf(x, w.y, acc[j][1]);
                acc[j][2] = fmaf(x, w.z, acc[j][2]);
                acc[j][3] = fmaf(x, w.w, acc[j][3]);
            }
        }
        const int ch   = tx * 4;
        const int head = tx >> 1;
        float4 b2 = *(const float4*)(xkb2 + ch);
#pragma unroll
        for (int j = 0; j < 8; j++) {
            int e = ty * 8 + j;
            int d = sdst[e];
            float4 qv = *(const float4*)(g_q + (size_t)d * 128 + ch);
            float part = (acc[j][0]+b2.x)*qv.x + (acc[j][1]+b2.y)*qv.y
                       + (acc[j][2]+b2.z)*qv.z + (acc[j][3]+b2.w)*qv.w;
            part += __shfl_xor_sync(0xffffffffu, part, 1);
            if ((tx & 1) == 0) {
                long ge = e0 + e;
                if (ge < E) {
                    float sv = part * 0.35355339059327373f; // 1/sqrt(8)
                    g_s[ge * 16 + head] = sv;
                    atomicMaxFloat(&g_smax[d * 16 + head], sv);
                }
            }
        }
    }

    // -------- Phase B2: v = (U_v @ Wv2 + b) * e_w --------
    {
        const int e  = tid >> 2;
        const int cb = (tid & 3) * 4;
        float a0=0.f, a1=0.f, a2=0.f, a3=0.f;
        const float* up = Us + e * US + 128;
        const float* wv = Ws + 16384 + cb;
#pragma unroll 4
        for (int k = 0; k < 128; k++) {
            float u = up[k];
            float4 w = *(const float4*)(wv + k * 16);
            a0 = fmaf(u, w.x, a0); a1 = fmaf(u, w.y, a1);
            a2 = fmaf(u, w.z, a2); a3 = fmaf(u, w.w, a3);
        }
        long ge = e0 + e;
        if (ge < E) {
            float w8 = ews[e];
            float4 bv = *(const float4*)(xvb2 + cb);
            float4 o = make_float4((a0+bv.x)*w8, (a1+bv.y)*w8, (a2+bv.z)*w8, (a3+bv.w)*w8);
            *(float4*)(g_vw + ge * 16 + cb) = o;
        }
    }
}

// ---------------- scatter softmax + weighted accumulation ----------------
__global__ void softmax_scatter_kernel(const float* __restrict__ rel_x,
                                       const int* __restrict__ eidx, int E)
{
    int i = blockIdx.x * blockDim.x + threadIdx.x;  // over E*16
    if (i >= E * 16) return;
    int h = i & 15;
    int e = i >> 4;
    int d = eidx[E + e];
    float s  = g_s[i];
    float mx = g_smax[d * 16 + h];
    float ex = __expf(s - mx);
    float vv = g_vw[i] * ex;
    atomicAdd(&g_den[d * 16 + h], ex);
    float rx = rel_x[e * 3 + 0], ry = rel_x[e * 3 + 1], rz = rel_x[e * 3 + 2];
    float* np = g_num + (size_t)(d * 16 + h) * 3;
    atomicAdd(np + 0, vv * rx);
    atomicAdd(np + 1, vv * ry);
    atomicAdd(np + 2, vv * rz);
}

// ---------------- finalize: mean over heads of num/den ----------------
__global__ void out_kernel(float* __restrict__ out, int N) {
    int n = blockIdx.x * blockDim.x + threadIdx.x;
    if (n >= N) return;
    float ox = 0.f, oy = 0.f, oz = 0.f;
#pragma unroll
    for (int h = 0; h < 16; h++) {
        float den = g_den[n * 16 + h];
        float inv = (den > 0.f) ? (1.0f / den) : 0.0f;
        const float* np = g_num + (size_t)(n * 16 + h) * 3;
        ox = fmaf(np[0], inv, ox);
        oy = fmaf(np[1], inv, oy);
        oz = fmaf(np[2], inv, oz);
    }
    out[n * 3 + 0] = ox * 0.0625f;
    out[n * 3 + 1] = oy * 0.0625f;
    out[n * 3 + 2] = oz * 0.0625f;
}

// ---------------- launch ----------------
extern "C" void kernel_launch(void* const* d_in, const int* in_sizes, int n_in,
                              void* d_out, int out_size)
{
    const float* h         = (const float*)d_in[0];
    const float* rel_x     = (const float*)d_in[1];
    const float* r_feat    = (const float*)d_in[2];
    const float* edge_feat = (const float*)d_in[3];
    const int*   eidx      = (const int*)  d_in[4];
    const float* xkW1 = (const float*)d_in[5];
    const float* xkb1 = (const float*)d_in[6];
    const float* xkg  = (const float*)d_in[7];
    const float* xkbe = (const float*)d_in[8];
    const float* xkW2 = (const float*)d_in[9];
    const float* xkb2 = (const float*)d_in[10];
    const float* xvW1 = (const float*)d_in[11];
    const float* xvb1 = (const float*)d_in[12];
    const float* xvg  = (const float*)d_in[13];
    const float* xvbe = (const float*)d_in[14];
    const float* xvW2 = (const float*)d_in[15];
    const float* xvb2 = (const float*)d_in[16];
    const float* xqW1 = (const float*)d_in[17];
    const float* xqb1 = (const float*)d_in[18];
    const float* xqg  = (const float*)d_in[19];
    const float* xqbe = (const float*)d_in[20];
    const float* xqW2 = (const float*)d_in[21];
    const float* xqb2 = (const float*)d_in[22];
    const float* ewW  = (const float*)d_in[23];
    const float* ewb  = (const float*)d_in[24];

    const int N = in_sizes[0] / 128;  // nodes
    const int E = in_sizes[2] / 64;   // edges (from r_feat)

    cudaFuncSetAttribute(node_kernel, cudaFuncAttributeMaxDynamicSharedMemorySize, NODE_SMEM_BYTES);
    cudaFuncSetAttribute(edge_kernel, cudaFuncAttributeMaxDynamicSharedMemorySize, EDGE_SMEM_BYTES);

    init_kernel<<<(N * 48 + 255) / 256, 256>>>(N);

    node_kernel<<<(N + 63) / 64, 256, NODE_SMEM_BYTES>>>(
        h, xkW1, xvW1, xqW1, xqb1, xqg, xqbe, xqW2, xqb2, N);

    edge_kernel<<<(E + 63) / 64, 256, EDGE_SMEM_BYTES>>>(
        edge_feat, r_feat, eidx,
        xkW1, xkb1, xkg, xkbe, xkW2, xkb2,
        xvW1, xvb1, xvg, xvbe, xvW2, xvb2,
        ewW, ewb, E);

    softmax_scatter_kernel<<<(E * 16 + 255) / 256, 256>>>(rel_x, eidx, E);

    out_kernel<<<(N + 255) / 256, 256>>>((float*)d_out, N);
}

// round 11
// speedup vs baseline: 1.4549x; 1.4549x over previous
#include <cuda_runtime.h>
#include <cuda_bf16.h>

// Problem constants (fixed by the dataset)
#define MAXN 50000
#define MAXE 800000

// ---------------- scratch (__device__ globals; allocation-free) ----------------
__device__ float g_q [MAXN * 128];
__device__ float g_Ak[MAXN * 128];
__device__ float g_Bk[MAXN * 128];
__device__ float g_Av[MAXN * 128];
__device__ float g_Bv[MAXN * 128];
__device__ float g_s  [(size_t)MAXE * 16];
__device__ float g_vw [(size_t)MAXE * 16];
__device__ float g_smax[MAXN * 16];
__device__ float g_den [MAXN * 16];
__device__ float g_num [MAXN * 48];

__device__ __forceinline__ void atomicMaxFloat(float* addr, float val) {
    // valid for mixed signs with init = -inf
    if (val >= 0.0f) atomicMax((int*)addr, __float_as_int(val));
    else             atomicMin((unsigned int*)addr, __float_as_uint(val));
}

// ---------------- init ----------------
__global__ void init_kernel(int N) {
    int i = blockIdx.x * blockDim.x + threadIdx.x;
    if (i < N * 16) {
        g_smax[i] = __int_as_float(0xff800000u); // -inf
        g_den[i]  = 0.0f;
    }
    if (i < N * 48) g_num[i] = 0.0f;
}

// ---------------- shared 64x128 register-tiled GEMM helper (node kernel) ----------------
__device__ __forceinline__ void gemm64x128(const float* __restrict__ Ws,
                                           const float* __restrict__ Xs,
                                           int tx, int ty, float acc[8][4]) {
#pragma unroll
    for (int j = 0; j < 8; j++) { acc[j][0]=0.f; acc[j][1]=0.f; acc[j][2]=0.f; acc[j][3]=0.f; }
    const float* wp = Ws + tx * 4;
    const float* xp = Xs + (ty * 8) * 128;
#pragma unroll 4
    for (int k = 0; k < 128; k++) {
        float4 w = *(const float4*)(wp + k * 128);
#pragma unroll
        for (int j = 0; j < 8; j++) {
            float x = xp[j * 128 + k];
            acc[j][0] = fmaf(x, w.x, acc[j][0]);
            acc[j][1] = fmaf(x, w.y, acc[j][1]);
            acc[j][2] = fmaf(x, w.z, acc[j][2]);
            acc[j][3] = fmaf(x, w.w, acc[j][3]);
        }
    }
}

// ---------------- node kernel: q (full MLP) + Ak/Bk/Av/Bv ----------------
#define NODE_SMEM_BYTES ((64*128 + 128*128) * 4)

__global__ void __launch_bounds__(256) node_kernel(
    const float* __restrict__ h,
    const float* __restrict__ xkW1, const float* __restrict__ xvW1,
    const float* __restrict__ xqW1, const float* __restrict__ xqb1,
    const float* __restrict__ xqg,  const float* __restrict__ xqbe,
    const float* __restrict__ xqW2, const float* __restrict__ xqb2,
    int N)
{
    extern __shared__ float sm[];
    float* Hs = sm;            // 64*128  (reused as LN buffer for q path)
    float* Ws = sm + 64 * 128; // 128*128
    const int tid = threadIdx.x;
    const int n0  = blockIdx.x * 64;

    for (int idx = tid; idx < 64 * 128; idx += 256) {
        int r = idx >> 7, c = idx & 127;
        int n = n0 + r;
        Hs[idx] = (n < N) ? h[(size_t)n * 128 + c] : 0.0f;
    }
    const int tx = tid & 31, ty = tid >> 5;

    const float* srcs[4] = { xkW1 + 80*128, xkW1 + 208*128, xvW1 + 80*128, xvW1 + 208*128 };
    float* outs[4] = { g_Ak, g_Bk, g_Av, g_Bv };
    for (int m = 0; m < 4; m++) {
        __syncthreads();
        for (int idx = tid; idx < 128 * 128; idx += 256) Ws[idx] = srcs[m][idx];
        __syncthreads();
        float acc[8][4];
        gemm64x128(Ws, Hs, tx, ty, acc);
#pragma unroll
        for (int j = 0; j < 8; j++) {
            int n = n0 + ty * 8 + j;
            if (n < N) {
                float4 o = make_float4(acc[j][0], acc[j][1], acc[j][2], acc[j][3]);
                *(float4*)(outs[m] + (size_t)n * 128 + tx * 4) = o;
            }
        }
    }

    // q layer 1
    __syncthreads();
    for (int idx = tid; idx < 128 * 128; idx += 256) Ws[idx] = xqW1[idx];
    __syncthreads();
    {
        float acc[8][4];
        gemm64x128(Ws, Hs, tx, ty, acc);
        float4 b1 = *(const float4*)(xqb1 + tx * 4);
        __syncthreads();
#pragma unroll
        for (int j = 0; j < 8; j++) {
            int r = ty * 8 + j;
            float4 o = make_float4(acc[j][0]+b1.x, acc[j][1]+b1.y, acc[j][2]+b1.z, acc[j][3]+b1.w);
            *(float4*)(Hs + r * 128 + tx * 4) = o;
        }
    }
    __syncthreads();

    // LayerNorm + ReLU
    {
        const int lane = tid & 31, w = tid >> 5;
        for (int r = w; r < 64; r += 8) {
            float* row = Hs + r * 128;
            float v0 = row[lane], v1 = row[lane+32], v2 = row[lane+64], v3 = row[lane+96];
            float s1 = v0+v1+v2+v3;
            float s2 = v0*v0+v1*v1+v2*v2+v3*v3;
#pragma unroll
            for (int o = 16; o > 0; o >>= 1) {
                s1 += __shfl_xor_sync(0xffffffffu, s1, o);
                s2 += __shfl_xor_sync(0xffffffffu, s2, o);
            }
            float mean = s1 * 0.0078125f;
            float var  = fmaxf(s2 * 0.0078125f - mean * mean, 0.0f);
            float rstd = rsqrtf(var + 1e-5f);
            row[lane]    = fmaxf((v0-mean)*rstd*xqg[lane]    + xqbe[lane],    0.0f);
            row[lane+32] = fmaxf((v1-mean)*rstd*xqg[lane+32] + xqbe[lane+32], 0.0f);
            row[lane+64] = fmaxf((v2-mean)*rstd*xqg[lane+64] + xqbe[lane+64], 0.0f);
            row[lane+96] = fmaxf((v3-mean)*rstd*xqg[lane+96] + xqbe[lane+96], 0.0f);
        }
    }

    // q layer 2
    __syncthreads();
    for (int idx = tid; idx < 128 * 128; idx += 256) Ws[idx] = xqW2[idx];
    __syncthreads();
    {
        float acc[8][4];
        gemm64x128(Ws, Hs, tx, ty, acc);
        float4 b2 = *(const float4*)(xqb2 + tx * 4);
#pragma unroll
        for (int j = 0; j < 8; j++) {
            int n = n0 + ty * 8 + j;
            if (n < N) {
                float4 o = make_float4(acc[j][0]+b2.x, acc[j][1]+b2.y, acc[j][2]+b2.z, acc[j][3]+b2.w);
                *(float4*)(g_q + (size_t)n * 128 + tx * 4) = o;
            }
        }
    }
}

// ---------------- edge kernel (split nets: blockIdx.y 0=k, 1=v) ----------------
// Transposed activation layout UT[c][e] with XOR chunk swizzle:
//   float at UT[c*64 + ((( (e>>2) ^ ((c>>2)&7) ) << 2) | (e&3))]
// Column float4 (4 consecutive e) at UT[c*64 + ((e0>>2)^((c>>2)&7))*4].
//
// smem floats: R[16384] (phase A: W1[80][128] @0, X[80][64] @10240;
//                        phase B: W2 @0) | UT[8192] | misc[256]
#define EDGE_SMEM_FLOATS (16384 + 8192 + 256)
#define EDGE_SMEM_BYTES  (EDGE_SMEM_FLOATS * 4)

__global__ void __launch_bounds__(256, 2) edge_kernel(
    const float* __restrict__ ef, const float* __restrict__ rf,
    const int*   __restrict__ eidx,
    const float* __restrict__ xkW1, const float* __restrict__ xkb1,
    const float* __restrict__ xkg,  const float* __restrict__ xkbe,
    const float* __restrict__ xkW2, const float* __restrict__ xkb2,
    const float* __restrict__ xvW1, const float* __restrict__ xvb1,
    const float* __restrict__ xvg,  const float* __restrict__ xvbe,
    const float* __restrict__ xvW2, const float* __restrict__ xvb2,
    const float* __restrict__ ewW,  const float* __restrict__ ewb,
    int E)
{
    extern __shared__ float sm[];
    float* R    = sm;                 // 16384
    float* UT   = sm + 16384;         // 8192
    int*   sdst = (int*)(sm + 24576); // 64
    int*   ssrc = sdst + 64;          // 64
    float* ews  = (float*)(ssrc + 64);// 64
    float* ewWs = ews + 64;           // 64
    float* Xs   = R + 10240;          // [80][64]

    const int  tid = threadIdx.x;
    const bool isV = (blockIdx.y != 0);
    const long e0  = (long)blockIdx.x * 64;

    const float* W1  = isV ? xvW1 : xkW1;
    const float* b1p = isV ? xvb1 : xkb1;
    const float* gp  = isV ? xvg  : xkg;
    const float* bep = isV ? xvbe : xkbe;
    const float* Ap  = isV ? g_Av : g_Ak;
    const float* Bp  = isV ? g_Bv : g_Bk;

    if (tid < 64) {
        long ge = e0 + tid;
        ssrc[tid] = (ge < E) ? eidx[ge]     : 0;
        sdst[tid] = (ge < E) ? eidx[E + ge] : 0;
    }
    if (isV && tid >= 64 && tid < 128) ewWs[tid - 64] = ewW[tid - 64];

    // X tile [80][64] (clamped for tail safety); e innermost -> conflict-free STS
    for (int idx = tid; idx < 64 * 16; idx += 256) {
        int e = idx & 63, k = idx >> 6;
        long ge = e0 + e; if (ge > E - 1) ge = E - 1;
        Xs[k * 64 + e] = ef[ge * 16 + k];
    }
    for (int idx = tid; idx < 64 * 64; idx += 256) {
        int e = idx & 63, k = idx >> 6;
        long ge = e0 + e; if (ge > E - 1) ge = E - 1;
        Xs[(16 + k) * 64 + e] = rf[ge * 64 + k];
    }
    // phase-A weights: W1 rows 0..79 of this net
    for (int idx = tid; idx < 80 * 128; idx += 256) R[idx] = W1[idx];
    __syncthreads();

    const int tx = tid & 15;       // channel fragment
    const int ty = tid >> 4;       // edge fragment (0..15)
    const int cL = tx * 4, cH = cL + 64;
    const int eb = ty * 4;

    // -------- Phase A: U[64 edges][128 ch] = X[64][80] @ W1[80][128] + bias + node partials --------
    {
        float acc[4][8];
#pragma unroll
        for (int j = 0; j < 4; j++)
#pragma unroll
            for (int i = 0; i < 8; i++) acc[j][i] = 0.0f;

#pragma unroll 2
        for (int k = 0; k < 80; k++) {
            float4 w0 = *(const float4*)(R  + k * 128 + cL);
            float4 w1 = *(const float4*)(R  + k * 128 + cH);
            float4 x  = *(const float4*)(Xs + k * 64 + eb);
            float xs[4] = {x.x, x.y, x.z, x.w};
#pragma unroll
            for (int j = 0; j < 4; j++) {
                acc[j][0] = fmaf(xs[j], w0.x, acc[j][0]);
                acc[j][1] = fmaf(xs[j], w0.y, acc[j][1]);
                acc[j][2] = fmaf(xs[j], w0.z, acc[j][2]);
                acc[j][3] = fmaf(xs[j], w0.w, acc[j][3]);
                acc[j][4] = fmaf(xs[j], w1.x, acc[j][4]);
                acc[j][5] = fmaf(xs[j], w1.y, acc[j][5]);
                acc[j][6] = fmaf(xs[j], w1.z, acc[j][6]);
                acc[j][7] = fmaf(xs[j], w1.w, acc[j][7]);
            }
        }

        float4 bb0 = *(const float4*)(b1p + cL);
        float4 bb1 = *(const float4*)(b1p + cH);
#pragma unroll
        for (int j = 0; j < 4; j++) {
            int e = eb + j;
            int d = sdst[e], s = ssrc[e];
            const float* ap = Ap + (size_t)d * 128;
            const float* bp = Bp + (size_t)s * 128;
            float4 a0 = *(const float4*)(ap + cL);
            float4 a1 = *(const float4*)(ap + cH);
            float4 c0 = *(const float4*)(bp + cL);
            float4 c1 = *(const float4*)(bp + cH);
            acc[j][0] += bb0.x + a0.x + c0.x;
            acc[j][1] += bb0.y + a0.y + c0.y;
            acc[j][2] += bb0.z + a0.z + c0.z;
            acc[j][3] += bb0.w + a0.w + c0.w;
            acc[j][4] += bb1.x + a1.x + c1.x;
            acc[j][5] += bb1.y + a1.y + c1.y;
            acc[j][6] += bb1.z + a1.z + c1.z;
            acc[j][7] += bb1.w + a1.w + c1.w;
        }
        // transposed store with XOR swizzle (conflict-free)
#pragma unroll
        for (int i = 0; i < 8; i++) {
            int c = (i < 4) ? (cL + i) : (cH + i - 4);
            int chunk = ty ^ ((c >> 2) & 7);
            *(float4*)(UT + c * 64 + chunk * 4) =
                make_float4(acc[0][i], acc[1][i], acc[2][i], acc[3][i]);
        }
    }
    __syncthreads();

    // -------- load phase-B weights (overlaps LN below) + edge weights (v) --------
    if (!isV) {
        for (int idx = tid; idx < 128 * 128; idx += 256) R[idx] = xkW2[idx];
    } else {
        for (int idx = tid; idx < 128 * 16; idx += 256) R[idx] = xvW2[idx];
        if (tid < 64) {
            float a = ewb[0];
#pragma unroll 8
            for (int i = 0; i < 64; i++) a = fmaf(Xs[(16 + i) * 64 + tid], ewWs[i], a);
            ews[tid] = 1.0f / (1.0f + __expf(-a));
        }
    }

    // -------- LayerNorm + ReLU on UT (per-edge over 128 channels) --------
    {
        const int lane = tid & 31, w = tid >> 5;
        for (int e = w; e < 64; e += 8) {
            const int ech = (e >> 2), elo = (e & 3);
            int i0 = lane;      int a0i = i0 * 64 + (((ech ^ ((i0 >> 2) & 7)) << 2) | elo);
            int i1 = lane + 32; int a1i = i1 * 64 + (((ech ^ ((i1 >> 2) & 7)) << 2) | elo);
            int i2 = lane + 64; int a2i = i2 * 64 + (((ech ^ ((i2 >> 2) & 7)) << 2) | elo);
            int i3 = lane + 96; int a3i = i3 * 64 + (((ech ^ ((i3 >> 2) & 7)) << 2) | elo);
            float v0 = UT[a0i], v1 = UT[a1i], v2 = UT[a2i], v3 = UT[a3i];
            float s1 = v0+v1+v2+v3;
            float s2 = v0*v0+v1*v1+v2*v2+v3*v3;
#pragma unroll
            for (int o = 16; o > 0; o >>= 1) {
                s1 += __shfl_xor_sync(0xffffffffu, s1, o);
                s2 += __shfl_xor_sync(0xffffffffu, s2, o);
            }
            float mean = s1 * 0.0078125f;
            float var  = fmaxf(s2 * 0.0078125f - mean * mean, 0.0f);
            float rstd = rsqrtf(var + 1e-5f);
            UT[a0i] = fmaxf((v0-mean)*rstd*gp[i0] + bep[i0], 0.0f);
            UT[a1i] = fmaxf((v1-mean)*rstd*gp[i1] + bep[i1], 0.0f);
            UT[a2i] = fmaxf((v2-mean)*rstd*gp[i2] + bep[i2], 0.0f);
            UT[a3i] = fmaxf((v3-mean)*rstd*gp[i3] + bep[i3], 0.0f);
        }
    }
    __syncthreads();

    if (!isV) {
        // -------- Phase B1: k = U @ Wk2 + b ; s = dot(q[dst], k)/sqrt(8) ; segment max --------
        float acc[4][8];
#pragma unroll
        for (int j = 0; j < 4; j++)
#pragma unroll
            for (int i = 0; i < 8; i++) acc[j][i] = 0.0f;

        for (int k4 = 0; k4 < 32; k4++) {
            const float* xb = UT + k4 * 256 + ((ty ^ (k4 & 7)) << 2);
            const float* wb = R + k4 * 512;
#pragma unroll
            for (int i = 0; i < 4; i++) {
                float4 w0 = *(const float4*)(wb + i * 128 + cL);
                float4 w1 = *(const float4*)(wb + i * 128 + cH);
                float4 x  = *(const float4*)(xb + i * 64);
                float xs[4] = {x.x, x.y, x.z, x.w};
#pragma unroll
                for (int j = 0; j < 4; j++) {
                    acc[j][0] = fmaf(xs[j], w0.x, acc[j][0]);
                    acc[j][1] = fmaf(xs[j], w0.y, acc[j][1]);
                    acc[j][2] = fmaf(xs[j], w0.z, acc[j][2]);
                    acc[j][3] = fmaf(xs[j], w0.w, acc[j][3]);
                    acc[j][4] = fmaf(xs[j], w1.x, acc[j][4]);
                    acc[j][5] = fmaf(xs[j], w1.y, acc[j][5]);
                    acc[j][6] = fmaf(xs[j], w1.z, acc[j][6]);
                    acc[j][7] = fmaf(xs[j], w1.w, acc[j][7]);
                }
            }
        }
        float4 bL = *(const float4*)(xkb2 + cL);
        float4 bH = *(const float4*)(xkb2 + cH);
#pragma unroll
        for (int j = 0; j < 4; j++) {
            int e = eb + j;
            int d = sdst[e];
            const float* qp = g_q + (size_t)d * 128;
            float4 qL = *(const float4*)(qp + cL);
            float4 qH = *(const float4*)(qp + cH);
            float pL = (acc[j][0]+bL.x)*qL.x + (acc[j][1]+bL.y)*qL.y
                     + (acc[j][2]+bL.z)*qL.z + (acc[j][3]+bL.w)*qL.w;
            float pH = (acc[j][4]+bH.x)*qH.x + (acc[j][5]+bH.y)*qH.y
                     + (acc[j][6]+bH.z)*qH.z + (acc[j][7]+bH.w)*qH.w;
            pL += __shfl_xor_sync(0xffffffffu, pL, 1);
            pH += __shfl_xor_sync(0xffffffffu, pH, 1);
            if ((tx & 1) == 0) {
                long ge = e0 + e;
                if (ge < E) {
                    int hL = tx >> 1;             // 0..7 ; high half head = hL+8
                    float sL = pL * 0.35355339059327373f;
                    float sH = pH * 0.35355339059327373f;
                    g_s[ge * 16 + hL]     = sL;
                    g_s[ge * 16 + 8 + hL] = sH;
                    atomicMaxFloat(&g_smax[d * 16 + hL],     sL);
                    atomicMaxFloat(&g_smax[d * 16 + 8 + hL], sH);
                }
            }
        }
    } else {
        // -------- Phase B2: v = (U @ Wv2 + b) * e_w --------
        const int e  = tid >> 2;
        const int c4 = (tid & 3) * 4;
        const int ech = e >> 2, elo = e & 3;
        float a0 = 0.f, a1 = 0.f, a2 = 0.f, a3 = 0.f;
        for (int k4 = 0; k4 < 32; k4++) {
            const float* xb = UT + k4 * 256 + ((ech ^ (k4 & 7)) << 2) + elo;
            const float* wb = R + k4 * 64 + c4;
#pragma unroll
            for (int i = 0; i < 4; i++) {
                float u = xb[i * 64];
                float4 w = *(const float4*)(wb + i * 16);
                a0 = fmaf(u, w.x, a0); a1 = fmaf(u, w.y, a1);
                a2 = fmaf(u, w.z, a2); a3 = fmaf(u, w.w, a3);
            }
        }
        long ge = e0 + e;
        if (ge < E) {
            float w8 = ews[e];
            float4 bv = *(const float4*)(xvb2 + c4);
            float4 o = make_float4((a0+bv.x)*w8, (a1+bv.y)*w8, (a2+bv.z)*w8, (a3+bv.w)*w8);
            *(float4*)(g_vw + ge * 16 + c4) = o;
        }
    }
}

// ---------------- scatter softmax + weighted accumulation ----------------
__global__ void softmax_scatter_kernel(const float* __restrict__ rel_x,
                                       const int* __restrict__ eidx, int E)
{
    int i = blockIdx.x * blockDim.x + threadIdx.x;  // over E*16
    if (i >= E * 16) return;
    int h = i & 15;
    int e = i >> 4;
    int d = eidx[E + e];
    float s  = g_s[i];
    float mx = g_smax[d * 16 + h];
    float ex = __expf(s - mx);
    float vv = g_vw[i] * ex;
    atomicAdd(&g_den[d * 16 + h], ex);
    float rx = rel_x[e * 3 + 0], ry = rel_x[e * 3 + 1], rz = rel_x[e * 3 + 2];
    float* np = g_num + (size_t)(d * 16 + h) * 3;
    atomicAdd(np + 0, vv * rx);
    atomicAdd(np + 1, vv * ry);
    atomicAdd(np + 2, vv * rz);
}

// ---------------- finalize ----------------
__global__ void out_kernel(float* __restrict__ out, int N) {
    int n = blockIdx.x * blockDim.x + threadIdx.x;
    if (n >= N) return;
    float ox = 0.f, oy = 0.f, oz = 0.f;
#pragma unroll
    for (int h = 0; h < 16; h++) {
        float den = g_den[n * 16 + h];
        float inv = (den > 0.f) ? (1.0f / den) : 0.0f;
        const float* np = g_num + (size_t)(n * 16 + h) * 3;
        ox = fmaf(np[0], inv, ox);
        oy = fmaf(np[1], inv, oy);
        oz = fmaf(np[2], inv, oz);
    }
    out[n * 3 + 0] = ox * 0.0625f;
    out[n * 3 + 1] = oy * 0.0625f;
    out[n * 3 + 2] = oz * 0.0625f;
}

// ---------------- launch ----------------
extern "C" void kernel_launch(void* const* d_in, const int* in_sizes, int n_in,
                              void* d_out, int out_size)
{
    const float* h         = (const float*)d_in[0];
    const float* rel_x     = (const float*)d_in[1];
    const float* r_feat    = (const float*)d_in[2];
    const float* edge_feat = (const float*)d_in[3];
    const int*   eidx      = (const int*)  d_in[4];
    const float* xkW1 = (const float*)d_in[5];
    const float* xkb1 = (const float*)d_in[6];
    const float* xkg  = (const float*)d_in[7];
    const float* xkbe = (const float*)d_in[8];
    const float* xkW2 = (const float*)d_in[9];
    const float* xkb2 = (const float*)d_in[10];
    const float* xvW1 = (const float*)d_in[11];
    const float* xvb1 = (const float*)d_in[12];
    const float* xvg  = (const float*)d_in[13];
    const float* xvbe = (const float*)d_in[14];
    const float* xvW2 = (const float*)d_in[15];
    const float* xvb2 = (const float*)d_in[16];
    const float* xqW1 = (const float*)d_in[17];
    const float* xqb1 = (const float*)d_in[18];
    const float* xqg  = (const float*)d_in[19];
    const float* xqbe = (const float*)d_in[20];
    const float* xqW2 = (const float*)d_in[21];
    const float* xqb2 = (const float*)d_in[22];
    const float* ewW  = (const float*)d_in[23];
    const float* ewb  = (const float*)d_in[24];

    const int N = in_sizes[0] / 128;  // nodes
    const int E = in_sizes[2] / 64;   // edges (from r_feat)

    cudaFuncSetAttribute(node_kernel, cudaFuncAttributeMaxDynamicSharedMemorySize, NODE_SMEM_BYTES);
    cudaFuncSetAttribute(edge_kernel, cudaFuncAttributeMaxDynamicSharedMemorySize, EDGE_SMEM_BYTES);

    init_kernel<<<(N * 48 + 255) / 256, 256>>>(N);

    node_kernel<<<(N + 63) / 64, 256, NODE_SMEM_BYTES>>>(
        h, xkW1, xvW1, xqW1, xqb1, xqg, xqbe, xqW2, xqb2, N);

    dim3 egrid((E + 63) / 64, 2);
    edge_kernel<<<egrid, 256, EDGE_SMEM_BYTES>>>(
        edge_feat, r_feat, eidx,
        xkW1, xkb1, xkg, xkbe, xkW2, xkb2,
        xvW1, xvb1, xvg, xvbe, xvW2, xvb2,
        ewW, ewb, E);

    softmax_scatter_kernel<<<(E * 16 + 255) / 256, 256>>>(rel_x, eidx, E);

    out_kernel<<<(N + 255) / 256, 256>>>((float*)d_out, N);
}

// round 12
// speedup vs baseline: 1.4607x; 1.0040x over previous
#include <cuda_runtime.h>
#include <cuda_bf16.h>

// Problem constants (fixed by the dataset)
#define MAXN 50000
#define MAXE 800000

// ---------------- scratch (__device__ globals; allocation-free) ----------------
__device__ float g_q [MAXN * 128];
__device__ float g_Ak[MAXN * 128];
__device__ float g_Bk[MAXN * 128];
__device__ float g_Av[MAXN * 128];
__device__ float g_Bv[MAXN * 128];
__device__ float g_s  [(size_t)MAXE * 16];
__device__ float g_vw [(size_t)MAXE * 16];
__device__ float g_smax[MAXN * 16];
__device__ float g_den [MAXN * 16];
__device__ float g_num [MAXN * 48];

__device__ __forceinline__ void atomicMaxFloat(float* addr, float val) {
    // valid for mixed signs with init = -inf
    if (val >= 0.0f) atomicMax((int*)addr, __float_as_int(val));
    else             atomicMin((unsigned int*)addr, __float_as_uint(val));
}

// ---------------- init ----------------
__global__ void init_kernel(int N) {
    int i = blockIdx.x * blockDim.x + threadIdx.x;
    if (i < N * 16) {
        g_smax[i] = __int_as_float(0xff800000u); // -inf
        g_den[i]  = 0.0f;
    }
    if (i < N * 48) g_num[i] = 0.0f;
}

// ---------------- shared 64x128 register-tiled GEMM helper (node kernel) ----------------
__device__ __forceinline__ void gemm64x128(const float* __restrict__ Ws,
                                           const float* __restrict__ Xs,
                                           int tx, int ty, float acc[8][4]) {
#pragma unroll
    for (int j = 0; j < 8; j++) { acc[j][0]=0.f; acc[j][1]=0.f; acc[j][2]=0.f; acc[j][3]=0.f; }
    const float* wp = Ws + tx * 4;
    const float* xp = Xs + (ty * 8) * 128;
#pragma unroll 4
    for (int k = 0; k < 128; k++) {
        float4 w = *(const float4*)(wp + k * 128);
#pragma unroll
        for (int j = 0; j < 8; j++) {
            float x = xp[j * 128 + k];
            acc[j][0] = fmaf(x, w.x, acc[j][0]);
            acc[j][1] = fmaf(x, w.y, acc[j][1]);
            acc[j][2] = fmaf(x, w.z, acc[j][2]);
            acc[j][3] = fmaf(x, w.w, acc[j][3]);
        }
    }
}

// ---------------- node kernel: q (full MLP) + Ak/Bk/Av/Bv ----------------
#define NODE_SMEM_BYTES ((64*128 + 128*128) * 4)

__global__ void __launch_bounds__(256) node_kernel(
    const float* __restrict__ h,
    const float* __restrict__ xkW1, const float* __restrict__ xvW1,
    const float* __restrict__ xqW1, const float* __restrict__ xqb1,
    const float* __restrict__ xqg,  const float* __restrict__ xqbe,
    const float* __restrict__ xqW2, const float* __restrict__ xqb2,
    int N)
{
    extern __shared__ float sm[];
    float* Hs = sm;            // 64*128  (reused as LN buffer for q path)
    float* Ws = sm + 64 * 128; // 128*128
    const int tid = threadIdx.x;
    const int n0  = blockIdx.x * 64;

    for (int idx = tid; idx < 64 * 128; idx += 256) {
        int r = idx >> 7, c = idx & 127;
        int n = n0 + r;
        Hs[idx] = (n < N) ? h[(size_t)n * 128 + c] : 0.0f;
    }
    const int tx = tid & 31, ty = tid >> 5;

    const float* srcs[4] = { xkW1 + 80*128, xkW1 + 208*128, xvW1 + 80*128, xvW1 + 208*128 };
    float* outs[4] = { g_Ak, g_Bk, g_Av, g_Bv };
    for (int m = 0; m < 4; m++) {
        __syncthreads();
        for (int idx = tid; idx < 128 * 128; idx += 256) Ws[idx] = srcs[m][idx];
        __syncthreads();
        float acc[8][4];
        gemm64x128(Ws, Hs, tx, ty, acc);
#pragma unroll
        for (int j = 0; j < 8; j++) {
            int n = n0 + ty * 8 + j;
            if (n < N) {
                float4 o = make_float4(acc[j][0], acc[j][1], acc[j][2], acc[j][3]);
                *(float4*)(outs[m] + (size_t)n * 128 + tx * 4) = o;
            }
        }
    }

    // q layer 1
    __syncthreads();
    for (int idx = tid; idx < 128 * 128; idx += 256) Ws[idx] = xqW1[idx];
    __syncthreads();
    {
        float acc[8][4];
        gemm64x128(Ws, Hs, tx, ty, acc);
        float4 b1 = *(const float4*)(xqb1 + tx * 4);
        __syncthreads();
#pragma unroll
        for (int j = 0; j < 8; j++) {
            int r = ty * 8 + j;
            float4 o = make_float4(acc[j][0]+b1.x, acc[j][1]+b1.y, acc[j][2]+b1.z, acc[j][3]+b1.w);
            *(float4*)(Hs + r * 128 + tx * 4) = o;
        }
    }
    __syncthreads();

    // LayerNorm + ReLU
    {
        const int lane = tid & 31, w = tid >> 5;
        for (int r = w; r < 64; r += 8) {
            float* row = Hs + r * 128;
            float v0 = row[lane], v1 = row[lane+32], v2 = row[lane+64], v3 = row[lane+96];
            float s1 = v0+v1+v2+v3;
            float s2 = v0*v0+v1*v1+v2*v2+v3*v3;
#pragma unroll
            for (int o = 16; o > 0; o >>= 1) {
                s1 += __shfl_xor_sync(0xffffffffu, s1, o);
                s2 += __shfl_xor_sync(0xffffffffu, s2, o);
            }
            float mean = s1 * 0.0078125f;
            float var  = fmaxf(s2 * 0.0078125f - mean * mean, 0.0f);
            float rstd = rsqrtf(var + 1e-5f);
            row[lane]    = fmaxf((v0-mean)*rstd*xqg[lane]    + xqbe[lane],    0.0f);
            row[lane+32] = fmaxf((v1-mean)*rstd*xqg[lane+32] + xqbe[lane+32], 0.0f);
            row[lane+64] = fmaxf((v2-mean)*rstd*xqg[lane+64] + xqbe[lane+64], 0.0f);
            row[lane+96] = fmaxf((v3-mean)*rstd*xqg[lane+96] + xqbe[lane+96], 0.0f);
        }
    }

    // q layer 2
    __syncthreads();
    for (int idx = tid; idx < 128 * 128; idx += 256) Ws[idx] = xqW2[idx];
    __syncthreads();
    {
        float acc[8][4];
        gemm64x128(Ws, Hs, tx, ty, acc);
        float4 b2 = *(const float4*)(xqb2 + tx * 4);
#pragma unroll
        for (int j = 0; j < 8; j++) {
            int n = n0 + ty * 8 + j;
            if (n < N) {
                float4 o = make_float4(acc[j][0]+b2.x, acc[j][1]+b2.y, acc[j][2]+b2.z, acc[j][3]+b2.w);
                *(float4*)(g_q + (size_t)n * 128 + tx * 4) = o;
            }
        }
    }
}

// ---------------- edge kernel (split nets: blockIdx.y 0=k, 1=v) ----------------
// Transposed activation layout UT[c][e] with XOR chunk swizzle:
//   float at UT[c*64 + ((( (e>>2) ^ ((c>>2)&7) ) << 2) | (e&3))]
// Column float4 (4 consecutive e) at UT[c*64 + ((e0>>2)^((c>>2)&7))*4].
//
// smem floats: R[16384] (phase A: W1[80][128] @0, X[80][64] @10240;
//                        phase B: W2 @0) | UT[8192] | misc[256]
#define EDGE_SMEM_FLOATS (16384 + 8192 + 256)
#define EDGE_SMEM_BYTES  (EDGE_SMEM_FLOATS * 4)

__global__ void __launch_bounds__(256, 2) edge_kernel(
    const float* __restrict__ ef, const float* __restrict__ rf,
    const int*   __restrict__ eidx,
    const float* __restrict__ xkW1, const float* __restrict__ xkb1,
    const float* __restrict__ xkg,  const float* __restrict__ xkbe,
    const float* __restrict__ xkW2, const float* __restrict__ xkb2,
    const float* __restrict__ xvW1, const float* __restrict__ xvb1,
    const float* __restrict__ xvg,  const float* __restrict__ xvbe,
    const float* __restrict__ xvW2, const float* __restrict__ xvb2,
    const float* __restrict__ ewW,  const float* __restrict__ ewb,
    int E)
{
    extern __shared__ float sm[];
    float* R    = sm;                 // 16384
    float* UT   = sm + 16384;         // 8192
    int*   sdst = (int*)(sm + 24576); // 64
    int*   ssrc = sdst + 64;          // 64
    float* ews  = (float*)(ssrc + 64);// 64
    float* ewWs = ews + 64;           // 64
    float* Xs   = R + 10240;          // [80][64]

    const int  tid = threadIdx.x;
    const bool isV = (blockIdx.y != 0);
    const long e0  = (long)blockIdx.x * 64;

    const float* W1  = isV ? xvW1 : xkW1;
    const float* b1p = isV ? xvb1 : xkb1;
    const float* gp  = isV ? xvg  : xkg;
    const float* bep = isV ? xvbe : xkbe;
    const float* Ap  = isV ? g_Av : g_Ak;
    const float* Bp  = isV ? g_Bv : g_Bk;

    if (tid < 64) {
        long ge = e0 + tid;
        ssrc[tid] = (ge < E) ? eidx[ge]     : 0;
        sdst[tid] = (ge < E) ? eidx[E + ge] : 0;
    }
    if (isV && tid >= 64 && tid < 128) ewWs[tid - 64] = ewW[tid - 64];

    // X tile [80][64] (clamped for tail safety); e innermost -> conflict-free STS
    for (int idx = tid; idx < 64 * 16; idx += 256) {
        int e = idx & 63, k = idx >> 6;
        long ge = e0 + e; if (ge > E - 1) ge = E - 1;
        Xs[k * 64 + e] = ef[ge * 16 + k];
    }
    for (int idx = tid; idx < 64 * 64; idx += 256) {
        int e = idx & 63, k = idx >> 6;
        long ge = e0 + e; if (ge > E - 1) ge = E - 1;
        Xs[(16 + k) * 64 + e] = rf[ge * 64 + k];
    }
    // phase-A weights: W1 rows 0..79 of this net
    for (int idx = tid; idx < 80 * 128; idx += 256) R[idx] = W1[idx];
    __syncthreads();

    const int tx = tid & 15;       // channel fragment
    const int ty = tid >> 4;       // edge fragment (0..15)
    const int cL = tx * 4, cH = cL + 64;
    const int eb = ty * 4;

    // -------- Phase A: U[64 edges][128 ch] = X[64][80] @ W1[80][128] + bias + node partials --------
    {
        float acc[4][8];
#pragma unroll
        for (int j = 0; j < 4; j++)
#pragma unroll
            for (int i = 0; i < 8; i++) acc[j][i] = 0.0f;

#pragma unroll 2
        for (int k = 0; k < 80; k++) {
            float4 w0 = *(const float4*)(R  + k * 128 + cL);
            float4 w1 = *(const float4*)(R  + k * 128 + cH);
            float4 x  = *(const float4*)(Xs + k * 64 + eb);
            float xs[4] = {x.x, x.y, x.z, x.w};
#pragma unroll
            for (int j = 0; j < 4; j++) {
                acc[j][0] = fmaf(xs[j], w0.x, acc[j][0]);
                acc[j][1] = fmaf(xs[j], w0.y, acc[j][1]);
                acc[j][2] = fmaf(xs[j], w0.z, acc[j][2]);
                acc[j][3] = fmaf(xs[j], w0.w, acc[j][3]);
                acc[j][4] = fmaf(xs[j], w1.x, acc[j][4]);
                acc[j][5] = fmaf(xs[j], w1.y, acc[j][5]);
                acc[j][6] = fmaf(xs[j], w1.z, acc[j][6]);
                acc[j][7] = fmaf(xs[j], w1.w, acc[j][7]);
            }
        }

        float4 bb0 = *(const float4*)(b1p + cL);
        float4 bb1 = *(const float4*)(b1p + cH);
#pragma unroll
        for (int j = 0; j < 4; j++) {
            int e = eb + j;
            int d = sdst[e], s = ssrc[e];
            const float* ap = Ap + (size_t)d * 128;
            const float* bp = Bp + (size_t)s * 128;
            float4 a0 = *(const float4*)(ap + cL);
            float4 a1 = *(const float4*)(ap + cH);
            float4 c0 = *(const float4*)(bp + cL);
            float4 c1 = *(const float4*)(bp + cH);
            acc[j][0] += bb0.x + a0.x + c0.x;
            acc[j][1] += bb0.y + a0.y + c0.y;
            acc[j][2] += bb0.z + a0.z + c0.z;
            acc[j][3] += bb0.w + a0.w + c0.w;
            acc[j][4] += bb1.x + a1.x + c1.x;
            acc[j][5] += bb1.y + a1.y + c1.y;
            acc[j][6] += bb1.z + a1.z + c1.z;
            acc[j][7] += bb1.w + a1.w + c1.w;
        }
        // transposed store with XOR swizzle (conflict-free)
#pragma unroll
        for (int i = 0; i < 8; i++) {
            int c = (i < 4) ? (cL + i) : (cH + i - 4);
            int chunk = ty ^ ((c >> 2) & 7);
            *(float4*)(UT + c * 64 + chunk * 4) =
                make_float4(acc[0][i], acc[1][i], acc[2][i], acc[3][i]);
        }
    }
    __syncthreads();

    // -------- load phase-B weights (overlaps LN below) + edge weights (v) --------
    if (!isV) {
        for (int idx = tid; idx < 128 * 128; idx += 256) R[idx] = xkW2[idx];
    } else {
        for (int idx = tid; idx < 128 * 16; idx += 256) R[idx] = xvW2[idx];
        if (tid < 64) {
            float a = ewb[0];
#pragma unroll 8
            for (int i = 0; i < 64; i++) a = fmaf(Xs[(16 + i) * 64 + tid], ewWs[i], a);
            ews[tid] = 1.0f / (1.0f + __expf(-a));
        }
    }

    // -------- LayerNorm + ReLU on UT (per-edge over 128 channels) --------
    {
        const int lane = tid & 31, w = tid >> 5;
        for (int e = w; e < 64; e += 8) {
            const int ech = (e >> 2), elo = (e & 3);
            int i0 = lane;      int a0i = i0 * 64 + (((ech ^ ((i0 >> 2) & 7)) << 2) | elo);
            int i1 = lane + 32; int a1i = i1 * 64 + (((ech ^ ((i1 >> 2) & 7)) << 2) | elo);
            int i2 = lane + 64; int a2i = i2 * 64 + (((ech ^ ((i2 >> 2) & 7)) << 2) | elo);
            int i3 = lane + 96; int a3i = i3 * 64 + (((ech ^ ((i3 >> 2) & 7)) << 2) | elo);
            float v0 = UT[a0i], v1 = UT[a1i], v2 = UT[a2i], v3 = UT[a3i];
            float s1 = v0+v1+v2+v3;
            float s2 = v0*v0+v1*v1+v2*v2+v3*v3;
#pragma unroll
            for (int o = 16; o > 0; o >>= 1) {
                s1 += __shfl_xor_sync(0xffffffffu, s1, o);
                s2 += __shfl_xor_sync(0xffffffffu, s2, o);
            }
            float mean = s1 * 0.0078125f;
            float var  = fmaxf(s2 * 0.0078125f - mean * mean, 0.0f);
            float rstd = rsqrtf(var + 1e-5f);
            UT[a0i] = fmaxf((v0-mean)*rstd*gp[i0] + bep[i0], 0.0f);
            UT[a1i] = fmaxf((v1-mean)*rstd*gp[i1] + bep[i1], 0.0f);
            UT[a2i] = fmaxf((v2-mean)*rstd*gp[i2] + bep[i2], 0.0f);
            UT[a3i] = fmaxf((v3-mean)*rstd*gp[i3] + bep[i3], 0.0f);
        }
    }
    __syncthreads();

    if (!isV) {
        // -------- Phase B1: k = U @ Wk2 + b ; s = dot(q[dst], k)/sqrt(8) ; segment max --------
        float acc[4][8];
#pragma unroll
        for (int j = 0; j < 4; j++)
#pragma unroll
            for (int i = 0; i < 8; i++) acc[j][i] = 0.0f;

        for (int k4 = 0; k4 < 32; k4++) {
            const float* xb = UT + k4 * 256 + ((ty ^ (k4 & 7)) << 2);
            const float* wb = R + k4 * 512;
#pragma unroll
            for (int i = 0; i < 4; i++) {
                float4 w0 = *(const float4*)(wb + i * 128 + cL);
                float4 w1 = *(const float4*)(wb + i * 128 + cH);
                float4 x  = *(const float4*)(xb + i * 64);
                float xs[4] = {x.x, x.y, x.z, x.w};
#pragma unroll
                for (int j = 0; j < 4; j++) {
                    acc[j][0] = fmaf(xs[j], w0.x, acc[j][0]);
                    acc[j][1] = fmaf(xs[j], w0.y, acc[j][1]);
                    acc[j][2] = fmaf(xs[j], w0.z, acc[j][2]);
                    acc[j][3] = fmaf(xs[j], w0.w, acc[j][3]);
                    acc[j][4] = fmaf(xs[j], w1.x, acc[j][4]);
                    acc[j][5] = fmaf(xs[j], w1.y, acc[j][5]);
                    acc[j][6] = fmaf(xs[j], w1.z, acc[j][6]);
                    acc[j][7] = fmaf(xs[j], w1.w, acc[j][7]);
                }
            }
        }
        float4 bL = *(const float4*)(xkb2 + cL);
        float4 bH = *(const float4*)(xkb2 + cH);
#pragma unroll
        for (int j = 0; j < 4; j++) {
            int e = eb + j;
            int d = sdst[e];
            const float* qp = g_q + (size_t)d * 128;
            float4 qL = *(const float4*)(qp + cL);
            float4 qH = *(const float4*)(qp + cH);
            float pL = (acc[j][0]+bL.x)*qL.x + (acc[j][1]+bL.y)*qL.y
                     + (acc[j][2]+bL.z)*qL.z + (acc[j][3]+bL.w)*qL.w;
            float pH = (acc[j][4]+bH.x)*qH.x + (acc[j][5]+bH.y)*qH.y
                     + (acc[j][6]+bH.z)*qH.z + (acc[j][7]+bH.w)*qH.w;
            pL += __shfl_xor_sync(0xffffffffu, pL, 1);
            pH += __shfl_xor_sync(0xffffffffu, pH, 1);
            if ((tx & 1) == 0) {
                long ge = e0 + e;
                if (ge < E) {
                    int hL = tx >> 1;             // 0..7 ; high half head = hL+8
                    float sL = pL * 0.35355339059327373f;
                    float sH = pH * 0.35355339059327373f;
                    g_s[ge * 16 + hL]     = sL;
                    g_s[ge * 16 + 8 + hL] = sH;
                    atomicMaxFloat(&g_smax[d * 16 + hL],     sL);
                    atomicMaxFloat(&g_smax[d * 16 + 8 + hL], sH);
                }
            }
        }
    } else {
        // -------- Phase B2: v = (U @ Wv2 + b) * e_w --------
        const int e  = tid >> 2;
        const int c4 = (tid & 3) * 4;
        const int ech = e >> 2, elo = e & 3;
        float a0 = 0.f, a1 = 0.f, a2 = 0.f, a3 = 0.f;
        for (int k4 = 0; k4 < 32; k4++) {
            const float* xb = UT + k4 * 256 + ((ech ^ (k4 & 7)) << 2) + elo;
            const float* wb = R + k4 * 64 + c4;
#pragma unroll
            for (int i = 0; i < 4; i++) {
                float u = xb[i * 64];
                float4 w = *(const float4*)(wb + i * 16);
                a0 = fmaf(u, w.x, a0); a1 = fmaf(u, w.y, a1);
                a2 = fmaf(u, w.z, a2); a3 = fmaf(u, w.w, a3);
            }
        }
        long ge = e0 + e;
        if (ge < E) {
            float w8 = ews[e];
            float4 bv = *(const float4*)(xvb2 + c4);
            float4 o = make_float4((a0+bv.x)*w8, (a1+bv.y)*w8, (a2+bv.z)*w8, (a3+bv.w)*w8);
            *(float4*)(g_vw + ge * 16 + c4) = o;
        }
    }
}

// ---------------- scatter softmax + weighted accumulation ----------------
__global__ void softmax_scatter_kernel(const float* __restrict__ rel_x,
                                       const int* __restrict__ eidx, int E)
{
    int i = blockIdx.x * blockDim.x + threadIdx.x;  // over E*16
    if (i >= E * 16) return;
    int h = i & 15;
    int e = i >> 4;
    int d = eidx[E + e];
    float s  = g_s[i];
    float mx = g_smax[d * 16 + h];
    float ex = __expf(s - mx);
    float vv = g_vw[i] * ex;
    atomicAdd(&g_den[d * 16 + h], ex);
    float rx = rel_x[e * 3 + 0], ry = rel_x[e * 3 + 1], rz = rel_x[e * 3 + 2];
    float* np = g_num + (size_t)(d * 16 + h) * 3;
    atomicAdd(np + 0, vv * rx);
    atomicAdd(np + 1, vv * ry);
    atomicAdd(np + 2, vv * rz);
}

// ---------------- finalize ----------------
__global__ void out_kernel(float* __restrict__ out, int N) {
    int n = blockIdx.x * blockDim.x + threadIdx.x;
    if (n >= N) return;
    float ox = 0.f, oy = 0.f, oz = 0.f;
#pragma unroll
    for (int h = 0; h < 16; h++) {
        float den = g_den[n * 16 + h];
        float inv = (den > 0.f) ? (1.0f / den) : 0.0f;
        const float* np = g_num + (size_t)(n * 16 + h) * 3;
        ox = fmaf(np[0], inv, ox);
        oy = fmaf(np[1], inv, oy);
        oz = fmaf(np[2], inv, oz);
    }
    out[n * 3 + 0] = ox * 0.0625f;
    out[n * 3 + 1] = oy * 0.0625f;
    out[n * 3 + 2] = oz * 0.0625f;
}

// ---------------- launch ----------------
extern "C" void kernel_launch(void* const* d_in, const int* in_sizes, int n_in,
                              void* d_out, int out_size)
{
    const float* h         = (const float*)d_in[0];
    const float* rel_x     = (const float*)d_in[1];
    const float* r_feat    = (const float*)d_in[2];
    const float* edge_feat = (const float*)d_in[3];
    const int*   eidx      = (const int*)  d_in[4];
    const float* xkW1 = (const float*)d_in[5];
    const float* xkb1 = (const float*)d_in[6];
    const float* xkg  = (const float*)d_in[7];
    const float* xkbe = (const float*)d_in[8];
    const float* xkW2 = (const float*)d_in[9];
    const float* xkb2 = (const float*)d_in[10];
    const float* xvW1 = (const float*)d_in[11];
    const float* xvb1 = (const float*)d_in[12];
    const float* xvg  = (const float*)d_in[13];
    const float* xvbe = (const float*)d_in[14];
    const float* xvW2 = (const float*)d_in[15];
    const float* xvb2 = (const float*)d_in[16];
    const float* xqW1 = (const float*)d_in[17];
    const float* xqb1 = (const float*)d_in[18];
    const float* xqg  = (const float*)d_in[19];
    const float* xqbe = (const float*)d_in[20];
    const float* xqW2 = (const float*)d_in[21];
    const float* xqb2 = (const float*)d_in[22];
    const float* ewW  = (const float*)d_in[23];
    const float* ewb  = (const float*)d_in[24];

    const int N = in_sizes[0] / 128;  // nodes
    const int E = in_sizes[2] / 64;   // edges (from r_feat)

    cudaFuncSetAttribute(node_kernel, cudaFuncAttributeMaxDynamicSharedMemorySize, NODE_SMEM_BYTES);
    cudaFuncSetAttribute(edge_kernel, cudaFuncAttributeMaxDynamicSharedMemorySize, EDGE_SMEM_BYTES);

    init_kernel<<<(N * 48 + 255) / 256, 256>>>(N);

    node_kernel<<<(N + 63) / 64, 256, NODE_SMEM_BYTES>>>(
        h, xkW1, xvW1, xqW1, xqb1, xqg, xqbe, xqW2, xqb2, N);

    dim3 egrid((E + 63) / 64, 2);
    edge_kernel<<<egrid, 256, EDGE_SMEM_BYTES>>>(
        edge_feat, r_feat, eidx,
        xkW1, xkb1, xkg, xkbe, xkW2, xkb2,
        xvW1, xvb1, xvg, xvbe, xvW2, xvb2,
        ewW, ewb, E);

    softmax_scatter_kernel<<<(E * 16 + 255) / 256, 256>>>(rel_x, eidx, E);

    out_kernel<<<(N + 255) / 256, 256>>>((float*)d_out, N);
}